// round 10
// baseline (speedup 1.0000x reference)
#include <cuda_runtime.h>

#define Dm 1024
#define MAXB 8
#define SMAX 4096

// ---------------- scratch (zero-init at load; consumers reset for replay) ---
__device__ float g_u[MAXB * Dm];               // k1_u atomic acc (zeroed by k3b)
__device__ float g_xw[MAXB * Dm];              // k3b atomic acc (zeroed by ln2)
__device__ float g_r[MAXB * Dm];               // overwritten fully by k5
__device__ float g_accV[MAXB * Dm];            // Wv acc (zeroed by ln2)
__device__ float g_accD[MAXB * Dm];            // Wd acc (zeroed by ln2)
__device__ float g_sc[MAXB * SMAX];            // scores (overwritten by k3a)

// ---------------- block reductions ------------------------------------------
__device__ __forceinline__ float blk_reduce(float v, volatile float* sbuf) {
    int lane = threadIdx.x & 31, w = threadIdx.x >> 5;
#pragma unroll
    for (int o = 16; o; o >>= 1) v += __shfl_xor_sync(0xffffffffu, v, o);
    __syncthreads();
    if (lane == 0) sbuf[w] = v;
    __syncthreads();
    int nw = blockDim.x >> 5;
    if (w == 0) {
        float r = (lane < nw) ? sbuf[lane] : 0.f;
#pragma unroll
        for (int o = 16; o; o >>= 1) r += __shfl_xor_sync(0xffffffffu, r, o);
        if (lane == 0) sbuf[0] = r;
    }
    __syncthreads();
    return sbuf[0];
}

__device__ __forceinline__ float blk_rmax(float v, volatile float* sbuf) {
    int lane = threadIdx.x & 31, w = threadIdx.x >> 5;
#pragma unroll
    for (int o = 16; o; o >>= 1) v = fmaxf(v, __shfl_xor_sync(0xffffffffu, v, o));
    __syncthreads();
    if (lane == 0) sbuf[w] = v;
    __syncthreads();
    int nw = blockDim.x >> 5;
    if (w == 0) {
        float r = (lane < nw) ? sbuf[lane] : -1e30f;
#pragma unroll
        for (int o = 16; o; o >>= 1) r = fmaxf(r, __shfl_xor_sync(0xffffffffu, r, o));
        if (lane == 0) sbuf[0] = r;
    }
    __syncthreads();
    return sbuf[0];
}

// ---------------- k1_u: u = Wk @ (x0@Wq + bq), fused, 32 blocks --------------
// Block owns e-chunk [e0,e0+32): computes q0c[b][e] then scatters into u atomically.
__global__ void __launch_bounds__(256) k1_u(const float* __restrict__ x, long xstride,
                                            const float* __restrict__ Wq,
                                            const float* __restrict__ bq,
                                            const float* __restrict__ Wk,
                                            float* __restrict__ u) {
    __shared__ float x0s[MAXB][Dm];              // 32 KB
    __shared__ float q0c[MAXB][32];
    int tid = threadIdx.x;
    int e0 = blockIdx.x * 32;

    for (int i = tid; i < MAXB * Dm; i += 256)
        x0s[i >> 10][i & (Dm - 1)] = x[(long)(i >> 10) * xstride + (i & (Dm - 1))];
    __syncthreads();

    // phase 1: q0c[b][e] = x0[b,:] . Wq[:,e0+e] + bq[e0+e]
    {
        int b = tid >> 5, e = tid & 31;
        float q = bq[e0 + e];
#pragma unroll 8
        for (int c = 0; c < Dm; c++)
            q = fmaf(x0s[b][c], Wq[(long)c * Dm + e0 + e], q);
        q0c[b][e] = q;
    }
    __syncthreads();

    // phase 2: u[b,d] += Wk[d, e0:e0+32] . q0c[b,:]
#pragma unroll
    for (int k = 0; k < 4; k++) {
        int d = k * 256 + tid;
        const float4* wk = (const float4*)(Wk + (long)d * Dm + e0);
        float acc[MAXB];
#pragma unroll
        for (int b = 0; b < MAXB; b++) acc[b] = 0.f;
#pragma unroll
        for (int i = 0; i < 8; i++) {
            float4 w = wk[i];
#pragma unroll
            for (int b = 0; b < MAXB; b++) {
                acc[b] += w.x * q0c[b][i * 4 + 0] + w.y * q0c[b][i * 4 + 1]
                        + w.z * q0c[b][i * 4 + 2] + w.w * q0c[b][i * 4 + 3];
            }
        }
#pragma unroll
        for (int b = 0; b < MAXB; b++)
            atomicAdd(&u[(long)b * Dm + d], acc[b]);
    }
}

// ---------------- k3a: pure score stream (unchanged from R7/R9) --------------
__global__ void __launch_bounds__(256) k3a(const float* __restrict__ x,
                                           const float* __restrict__ ug,
                                           float* __restrict__ sc, int S) {
    int b = blockIdx.y;
    int wid = threadIdx.x >> 5, lane = threadIdx.x & 31;
    int tbase = blockIdx.x * 32 + wid * 4;
    const float4* x0 = (const float4*)x + ((long)b * S + tbase) * 256;
#pragma unroll
    for (int i = 0; i < 8; i++)
        asm volatile("prefetch.global.L2 [%0];" :: "l"(x0 + lane + 32 * i));
    cudaGridDependencySynchronize();
    const float4* ub = (const float4*)(ug + (long)b * Dm);
    float4 uv[8];
#pragma unroll
    for (int i = 0; i < 8; i++) uv[i] = __ldg(ub + lane + 32 * i);
#pragma unroll
    for (int k = 0; k < 4; k++) {
        const float4* xr = x0 + (long)k * 256;
        float d = 0.f;
#pragma unroll
        for (int i = 0; i < 8; i++) {
            float4 xv = xr[lane + 32 * i];
            d += xv.x * uv[i].x + xv.y * uv[i].y + xv.z * uv[i].z + xv.w * uv[i].w;
        }
#pragma unroll
        for (int o = 16; o; o >>= 1) d += __shfl_xor_sync(0xffffffffu, d, o);
        if (lane == 0) sc[(long)b * S + tbase + k] = d * 0.03125f;  // 1/sqrt(1024)
    }
}

// ---------------- k3b: softmax + weighted accumulate; zero u -----------------
__global__ void __launch_bounds__(256) k3b(const float* __restrict__ x,
                                           const float* __restrict__ scg,
                                           float* __restrict__ xw,
                                           float* __restrict__ ureset, int S) {
    __shared__ float w[128];
    __shared__ float sbuf[32];
    __shared__ float4 redb[4][64];
    int b = blockIdx.y;
    int ntc = S >> 7;
    int tc = blockIdx.x % ntc, jc = blockIdx.x / ntc;
    int tid = threadIdx.x;
    cudaGridDependencySynchronize();
    if (blockIdx.x == 0)                              // zero u[b,:] (k3a done)
        ((float4*)ureset)[b * 256 + tid] = make_float4(0.f, 0.f, 0.f, 0.f);

    const float* sb = scg + (long)b * S;
    float m = -1e30f;
    for (int t = tid; t < S; t += 256) m = fmaxf(m, sb[t]);
    m = blk_rmax(m, sbuf);
    float s = 0.f;
    for (int t = tid; t < S; t += 256) s += __expf(sb[t] - m);
    s = blk_reduce(s, sbuf);
    float zinv = 1.f / s;
    if (tid < 128) w[tid] = __expf(sb[tc * 128 + tid] - m) * zinv;
    __syncthreads();

    int tg = tid >> 6, jj = tid & 63;
    int j4 = jc * 64 + jj;
    const float4* xb = (const float4*)x + ((long)b * S + tc * 128) * 256;
    float4 acc = make_float4(0.f, 0.f, 0.f, 0.f);
#pragma unroll 8
    for (int t = tg; t < 128; t += 4) {
        float p = w[t];
        float4 xv = xb[(long)t * 256 + j4];
        acc.x = fmaf(p, xv.x, acc.x);
        acc.y = fmaf(p, xv.y, acc.y);
        acc.z = fmaf(p, xv.z, acc.z);
        acc.w = fmaf(p, xv.w, acc.w);
    }
    redb[tg][jj] = acc;
    __syncthreads();
    if (tg == 0) {
        float4 t0 = redb[0][jj];
#pragma unroll
        for (int p = 1; p < 4; p++) {
            float4 v = redb[p][jj];
            t0.x += v.x; t0.y += v.y; t0.z += v.z; t0.w += v.w;
        }
        float* dst = &xw[(long)b * Dm + j4 * 4];
        atomicAdd(dst + 0, t0.x);
        atomicAdd(dst + 1, t0.y);
        atomicAdd(dst + 2, t0.z);
        atomicAdd(dst + 3, t0.w);
    }
}

// ---------------- gemv_pdl: accV += xw @ Wv ----------------------------------
__global__ void __launch_bounds__(256) gemv_pdl(const float* __restrict__ A,
                                                long astride,
                                                const float* __restrict__ W,
                                                float* __restrict__ accout, int B) {
    __shared__ float as[MAXB][32];
    int j  = blockIdx.x * 256 + threadIdx.x;
    int d0 = blockIdx.y * 32;
    float wv[32];
#pragma unroll
    for (int dd = 0; dd < 32; dd++) wv[dd] = W[(long)(d0 + dd) * Dm + j];
    cudaGridDependencySynchronize();
    {
        int b = threadIdx.x >> 5, dd = threadIdx.x & 31;
        as[b][dd] = (b < B) ? A[(long)b * astride + d0 + dd] : 0.f;
    }
    __syncthreads();
    float acc[MAXB];
#pragma unroll
    for (int b = 0; b < MAXB; b++) acc[b] = 0.f;
#pragma unroll
    for (int dd = 0; dd < 32; dd++) {
#pragma unroll
        for (int b = 0; b < MAXB; b++) acc[b] = fmaf(as[b][dd], wv[dd], acc[b]);
    }
    for (int b = 0; b < B; b++)
        atomicAdd(&accout[(long)b * Dm + j], acc[b]);
}

// ---------------- k5: fused LN1 + gemv(Wd) ------------------------------------
// grid (4, 32), 256 thr. Each block: redundant LN1 stats of v=accV+bv+x0,
// r-slice for its d-chunk, then accD[b,j] += r_slice . Wd[d0:d0+32, j].
// Blocks with jx==0 also write the r-slice to rout (for ln2 residual).
__global__ void __launch_bounds__(256) k5_lngemv(const float* __restrict__ accV,
                                                 const float* __restrict__ x, long xstride,
                                                 const float* __restrict__ bv,
                                                 const float* __restrict__ g1,
                                                 const float* __restrict__ b1,
                                                 const float* __restrict__ Wd,
                                                 float* __restrict__ rout,
                                                 float* __restrict__ accD) {
    __shared__ float rs[MAXB][32];
    __shared__ float muS[MAXB], rsS[MAXB];
    int tid = threadIdx.x;
    int jx = blockIdx.x, dc = blockIdx.y;
    int j = jx * 256 + tid, d0 = dc * 32;
    int b = tid >> 5, seg = tid & 31;

    // preloads independent of upstream (overlap under PDL)
    float wv[32];
#pragma unroll
    for (int k = 0; k < 32; k++) wv[k] = Wd[(long)(d0 + k) * Dm + j];
    float4 bv4[8], x04[8];
    const float4* bvv = (const float4*)bv + seg * 8;
    const float4* xvv = (const float4*)(x + (long)b * xstride) + seg * 8;
#pragma unroll
    for (int k = 0; k < 8; k++) { bv4[k] = bvv[k]; x04[k] = xvv[k]; }
    float g1s = g1[d0 + seg], b1s = b1[d0 + seg], bvs = bv[d0 + seg];
    float xs  = x[(long)b * xstride + d0 + seg];
    cudaGridDependencySynchronize();

    // LN1 stats: warp w == batch b; lanes cover the 1024-row in 32-float segs
    {
        const float4* av = (const float4*)(accV + (long)b * Dm) + seg * 8;
        float s1 = 0.f, s2 = 0.f;
#pragma unroll
        for (int k = 0; k < 8; k++) {
            float4 a = av[k];
            float v0 = a.x + bv4[k].x + x04[k].x;
            float v1 = a.y + bv4[k].y + x04[k].y;
            float v2 = a.z + bv4[k].z + x04[k].z;
            float v3 = a.w + bv4[k].w + x04[k].w;
            s1 += v0 + v1 + v2 + v3;
            s2 += v0 * v0 + v1 * v1 + v2 * v2 + v3 * v3;
        }
#pragma unroll
        for (int o = 16; o; o >>= 1) {
            s1 += __shfl_xor_sync(0xffffffffu, s1, o);
            s2 += __shfl_xor_sync(0xffffffffu, s2, o);
        }
        if (seg == 0) {
            float mu = s1 * (1.f / Dm);
            float var = s2 * (1.f / Dm) - mu * mu;
            muS[b] = mu;
            rsS[b] = rsqrtf(var + 1e-5f);
        }
    }
    __syncthreads();

    // r slice for this d-chunk
    {
        float v = accV[(long)b * Dm + d0 + seg] + bvs + xs;
        float rv = (v - muS[b]) * rsS[b] * g1s + b1s;
        rs[b][seg] = rv;
        if (jx == 0) rout[(long)b * Dm + d0 + seg] = rv;
    }
    __syncthreads();

    // gemv: accD[b,j] += rs[b,:] . wv[:]
    float acc[MAXB];
#pragma unroll
    for (int bb = 0; bb < MAXB; bb++) acc[bb] = 0.f;
#pragma unroll
    for (int dd = 0; dd < 32; dd++) {
#pragma unroll
        for (int bb = 0; bb < MAXB; bb++) acc[bb] = fmaf(rs[bb][dd], wv[dd], acc[bb]);
    }
#pragma unroll
    for (int bb = 0; bb < MAXB; bb++)
        atomicAdd(&accD[(long)bb * Dm + j], acc[bb]);
}

// ---------------- ln2: out = LN2(relu(accD+bd)+r)@Wc + bc; reset accs --------
__global__ void __launch_bounds__(1024) k_ln2(float* __restrict__ acc,
                                              const float* __restrict__ bd,
                                              const float* __restrict__ r,
                                              const float* __restrict__ g2,
                                              const float* __restrict__ b2,
                                              const float* __restrict__ Wc,
                                              const float* __restrict__ bc,
                                              float* __restrict__ accVz,
                                              float* __restrict__ xwz,
                                              float* __restrict__ out) {
    int b = blockIdx.x, j = threadIdx.x;
    __shared__ float sbuf[32];
    float gg = g2[j], bb = b2[j], bdj = bd[j];
    float w0 = Wc[j * 2 + 0], w1 = Wc[j * 2 + 1];
    cudaGridDependencySynchronize();
    float v = fmaxf(acc[(long)b * Dm + j] + bdj, 0.f) + r[(long)b * Dm + j];
    acc[(long)b * Dm + j]   = 0.f;                    // reset for next replay
    accVz[(long)b * Dm + j] = 0.f;
    xwz[(long)b * Dm + j]   = 0.f;
    float sum = blk_reduce(v, sbuf);
    float sq  = blk_reduce(v * v, sbuf);
    float mu  = sum * (1.f / Dm);
    float var = sq * (1.f / Dm) - mu * mu;
    float rstd = rsqrtf(var + 1e-5f);
    float h = (v - mu) * rstd * gg + bb;
    float l0 = blk_reduce(h * w0, sbuf);
    float l1 = blk_reduce(h * w1, sbuf);
    if (j == 0) {
        out[b * 2 + 0] = l0 + bc[0];
        out[b * 2 + 1] = l1 + bc[1];
    }
}

// ---------------- host --------------------------------------------------------
static void launch_ex(const void* fn, dim3 grid, dim3 block, void** args, bool pdl) {
    cudaLaunchConfig_t cfg = {};
    cfg.gridDim = grid;
    cfg.blockDim = block;
    cfg.dynamicSmemBytes = 0;
    cfg.stream = 0;
    cudaLaunchAttribute attr[1];
    attr[0].id = cudaLaunchAttributeProgrammaticStreamSerialization;
    attr[0].val.programmaticStreamSerializationAllowed = 1;
    cfg.attrs = attr;
    cfg.numAttrs = pdl ? 1 : 0;
    cudaLaunchKernelExC(&cfg, fn, args);
}

extern "C" void kernel_launch(void* const* d_in, const int* in_sizes, int n_in,
                              void* d_out, int out_size) {
    const float* x  = (const float*)d_in[0];
    const float* Wq = (const float*)d_in[1];
    const float* bq = (const float*)d_in[2];
    const float* Wk = (const float*)d_in[3];
    // d_in[4] = bk: constant over t in scores -> cancels in softmax; unused.
    const float* Wv = (const float*)d_in[5];
    const float* bv = (const float*)d_in[6];
    const float* Wd = (const float*)d_in[7];
    const float* bd = (const float*)d_in[8];
    const float* g1 = (const float*)d_in[9];
    const float* b1 = (const float*)d_in[10];
    const float* g2 = (const float*)d_in[11];
    const float* b2 = (const float*)d_in[12];
    const float* Wc = (const float*)d_in[13];
    const float* bc = (const float*)d_in[14];
    float* out = (float*)d_out;

    int  B   = out_size / 2;                       // 8
    long xsz = (long)in_sizes[0];
    int  S   = (int)(xsz / ((long)B * Dm));        // 2048
    long xstride = (long)S * Dm;

    float *u, *xw, *r, *accV, *accD, *sc;
    cudaGetSymbolAddress((void**)&u,    g_u);
    cudaGetSymbolAddress((void**)&xw,   g_xw);
    cudaGetSymbolAddress((void**)&r,    g_r);
    cudaGetSymbolAddress((void**)&accV, g_accV);
    cudaGetSymbolAddress((void**)&accD, g_accD);
    cudaGetSymbolAddress((void**)&sc,   g_sc);

    // 1. u = Wk @ (x0@Wq + bq)   (first kernel: starts loading at t=0)
    {
        void* a[] = {(void*)&x, (void*)&xstride, (void*)&Wq, (void*)&bq,
                     (void*)&Wk, (void*)&u};
        launch_ex((const void*)k1_u, dim3(32), dim3(256), a, false);
    }
    // 2. scores
    {
        void* a[] = {(void*)&x, (void*)&u, (void*)&sc, (void*)&S};
        launch_ex((const void*)k3a, dim3(S / 32, B), dim3(256), a, true);
    }
    // 3. softmax + weighted accumulate -> xw; zero u
    {
        void* a[] = {(void*)&x, (void*)&sc, (void*)&xw, (void*)&u, (void*)&S};
        launch_ex((const void*)k3b, dim3((S / 128) * 4, B), dim3(256), a, true);
    }
    // 4. accV += xw @ Wv
    {
        long st = Dm;
        void* a[] = {(void*)&xw, (void*)&st, (void*)&Wv, (void*)&accV, (void*)&B};
        launch_ex((const void*)gemv_pdl, dim3(4, 32), dim3(256), a, true);
    }
    // 5. fused: r = LN1(accV+bv+x0); accD += r @ Wd
    {
        void* a[] = {(void*)&accV, (void*)&x, (void*)&xstride, (void*)&bv,
                     (void*)&g1, (void*)&b1, (void*)&Wd, (void*)&r, (void*)&accD};
        launch_ex((const void*)k5_lngemv, dim3(4, 32), dim3(256), a, true);
    }
    // 6. out = LN2(relu(accD+bd)+r)@Wc + bc; zero accD, accV, xw
    {
        void* a[] = {(void*)&accD, (void*)&bd, (void*)&r, (void*)&g2, (void*)&b2,
                     (void*)&Wc, (void*)&bc, (void*)&accV, (void*)&xw, (void*)&out};
        launch_ex((const void*)k_ln2, dim3(B), dim3(1024), a, true);
    }
}

// round 11
// speedup vs baseline: 2.0207x; 2.0207x over previous
#include <cuda_runtime.h>

#define Dm 1024
#define MAXB 8
#define SMAX 4096

// ---------------- scratch (zero-init at load; consumers reset for replay) ---
__device__ float g_q0[MAXB * Dm];              // Wq acc (zeroed by k3a)
__device__ float g_u[MAXB * Dm];               // overwritten fully by k2_u
__device__ float g_xw[MAXB * Dm];              // k3b acc (zeroed by k_ln1)
__device__ float g_r[MAXB * Dm];               // overwritten fully by k_ln1
__device__ float g_accV[MAXB * Dm];            // Wv acc (zeroed by k_ln1)
__device__ float g_accD[MAXB * Dm];            // Wd acc (zeroed by k_ln2)
__device__ float g_sc[MAXB * SMAX];            // scores (overwritten by k3a)

// ---------------- block reductions ------------------------------------------
__device__ __forceinline__ float blk_reduce(float v, volatile float* sbuf) {
    int lane = threadIdx.x & 31, w = threadIdx.x >> 5;
#pragma unroll
    for (int o = 16; o; o >>= 1) v += __shfl_xor_sync(0xffffffffu, v, o);
    __syncthreads();
    if (lane == 0) sbuf[w] = v;
    __syncthreads();
    int nw = blockDim.x >> 5;
    if (w == 0) {
        float r = (lane < nw) ? sbuf[lane] : 0.f;
#pragma unroll
        for (int o = 16; o; o >>= 1) r += __shfl_xor_sync(0xffffffffu, r, o);
        if (lane == 0) sbuf[0] = r;
    }
    __syncthreads();
    return sbuf[0];
}

__device__ __forceinline__ float blk_rmax(float v, volatile float* sbuf) {
    int lane = threadIdx.x & 31, w = threadIdx.x >> 5;
#pragma unroll
    for (int o = 16; o; o >>= 1) v = fmaxf(v, __shfl_xor_sync(0xffffffffu, v, o));
    __syncthreads();
    if (lane == 0) sbuf[w] = v;
    __syncthreads();
    int nw = blockDim.x >> 5;
    if (w == 0) {
        float r = (lane < nw) ? sbuf[lane] : -1e30f;
#pragma unroll
        for (int o = 16; o; o >>= 1) r = fmaxf(r, __shfl_xor_sync(0xffffffffu, r, o));
        if (lane == 0) sbuf[0] = r;
    }
    __syncthreads();
    return sbuf[0];
}

// ---------------- PDL skinny GEMV: acc[b,j] += A[b,d0:d0+32] @ W -------------
// grid (8, 32), block 128 (256 blocks). W tile preloaded to regs BEFORE
// gridsync. Target buffer must be zero on entry.
__global__ void __launch_bounds__(128) gemv_pdl(const float* __restrict__ A,
                                                long astride,
                                                const float* __restrict__ W,
                                                float* __restrict__ accout, int B) {
    __shared__ float as[MAXB][32];
    int tid = threadIdx.x;
    int j  = blockIdx.x * 128 + tid;
    int d0 = blockIdx.y * 32;
    float wv[32];
#pragma unroll
    for (int dd = 0; dd < 32; dd++) wv[dd] = W[(long)(d0 + dd) * Dm + j];
    cudaGridDependencySynchronize();
    for (int i = tid; i < MAXB * 32; i += 128) {
        int b = i >> 5, dd = i & 31;
        as[b][dd] = (b < B) ? A[(long)b * astride + d0 + dd] : 0.f;
    }
    __syncthreads();
    float acc[MAXB];
#pragma unroll
    for (int b = 0; b < MAXB; b++) acc[b] = 0.f;
#pragma unroll
    for (int dd = 0; dd < 32; dd++) {
#pragma unroll
        for (int b = 0; b < MAXB; b++) acc[b] = fmaf(as[b][dd], wv[dd], acc[b]);
    }
    for (int b = 0; b < B; b++)
        atomicAdd(&accout[(long)b * Dm + j], acc[b]);
}

// ---------------- u[b,d] = Wk[d,:] . (q0[b,:] + bq) --------------------------
// 128 blocks x 8 warps (1 row each). Wk row preloaded to regs before gridsync.
__global__ void __launch_bounds__(256) k2_u(const float* __restrict__ Wk,
                                            const float* __restrict__ q0g,
                                            const float* __restrict__ bq,
                                            float* __restrict__ u) {
    __shared__ float4 q0s[MAXB * 256];               // 32 KB
    int wid = threadIdx.x >> 5, lane = threadIdx.x & 31;
    int d = blockIdx.x * 8 + wid;
    const float4* wrow = (const float4*)(Wk + (long)d * Dm);
    float4 wv[8];
#pragma unroll
    for (int i = 0; i < 8; i++) wv[i] = wrow[lane + 32 * i];
    cudaGridDependencySynchronize();
    for (int i = threadIdx.x; i < MAXB * 256; i += 256) {
        float4 q = ((const float4*)q0g)[i];
        float4 bb = ((const float4*)bq)[i & 255];
        q.x += bb.x; q.y += bb.y; q.z += bb.z; q.w += bb.w;
        q0s[i] = q;
    }
    __syncthreads();
    float acc[MAXB];
#pragma unroll
    for (int b = 0; b < MAXB; b++) acc[b] = 0.f;
#pragma unroll
    for (int i = 0; i < 8; i++) {
#pragma unroll
        for (int b = 0; b < MAXB; b++) {
            float4 q = q0s[b * 256 + lane + 32 * i];
            acc[b] += wv[i].x * q.x + wv[i].y * q.y + wv[i].z * q.z + wv[i].w * q.w;
        }
    }
#pragma unroll
    for (int b = 0; b < MAXB; b++)
#pragma unroll
        for (int o = 16; o; o >>= 1)
            acc[b] += __shfl_xor_sync(0xffffffffu, acc[b], o);
    if (lane == 0)
#pragma unroll
        for (int b = 0; b < MAXB; b++) u[(long)b * Dm + d] = acc[b];
}

// ---------------- k3a: pure score stream, 2 tokens/warp ----------------------
// grid (S/16, B) = 1024 blocks, 256 thr. Also resets q0 (k2_u done at gridsync).
__global__ void __launch_bounds__(256) k3a(const float* __restrict__ x,
                                           const float* __restrict__ ug,
                                           float* __restrict__ q0reset,
                                           float* __restrict__ sc, int S) {
    int b = blockIdx.y;
    int wid = threadIdx.x >> 5, lane = threadIdx.x & 31;
    int tbase = blockIdx.x * 16 + wid * 2;
    const float4* x0 = (const float4*)x + ((long)b * S + tbase) * 256;
#pragma unroll
    for (int k = 0; k < 2; k++)
#pragma unroll
        for (int i = 0; i < 8; i++)
            asm volatile("prefetch.global.L2 [%0];" :: "l"(x0 + k * 256 + lane + 32 * i));
    cudaGridDependencySynchronize();
    if (blockIdx.x == 0)                              // zero q0[b,:] for next run
        ((float4*)q0reset)[b * 256 + threadIdx.x] = make_float4(0.f, 0.f, 0.f, 0.f);
    const float4* ub = (const float4*)(ug + (long)b * Dm);
    float4 uv[8];
#pragma unroll
    for (int i = 0; i < 8; i++) uv[i] = __ldg(ub + lane + 32 * i);
#pragma unroll
    for (int k = 0; k < 2; k++) {
        const float4* xr = x0 + (long)k * 256;
        float d = 0.f;
#pragma unroll
        for (int i = 0; i < 8; i++) {
            float4 xv = xr[lane + 32 * i];
            d += xv.x * uv[i].x + xv.y * uv[i].y + xv.z * uv[i].z + xv.w * uv[i].w;
        }
#pragma unroll
        for (int o = 16; o; o >>= 1) d += __shfl_xor_sync(0xffffffffu, d, o);
        if (lane == 0) sc[(long)b * S + tbase + k] = d * 0.03125f;  // 1/sqrt(1024)
    }
}

// ---------------- k3b: softmax (redundant) + weighted accumulate ------------
// grid ((S/128)*8, B) = 1024 blocks, 256 thr. x re-read (L2). atomicAdd -> xw.
__global__ void __launch_bounds__(256) k3b(const float* __restrict__ x,
                                           const float* __restrict__ scg,
                                           float* __restrict__ xw, int S) {
    __shared__ float w[128];
    __shared__ float sbuf[32];
    __shared__ float4 redb[8][32];
    int b = blockIdx.y;
    int ntc = S >> 7;                                 // 128-token chunks (16)
    int tc = blockIdx.x % ntc, jc = blockIdx.x / ntc; // jc in 0..7
    int tid = threadIdx.x;
    cudaGridDependencySynchronize();

    const float* sb = scg + (long)b * S;
    float m = -1e30f;
    for (int t = tid; t < S; t += 256) m = fmaxf(m, sb[t]);
    m = blk_rmax(m, sbuf);
    float s = 0.f;
    for (int t = tid; t < S; t += 256) s += __expf(sb[t] - m);
    s = blk_reduce(s, sbuf);
    float zinv = 1.f / s;
    if (tid < 128) w[tid] = __expf(sb[tc * 128 + tid] - m) * zinv;
    __syncthreads();

    int tg = tid >> 5, jj = tid & 31;                 // 8 token-partitions x 32 j4
    int j4 = jc * 32 + jj;
    const float4* xb = (const float4*)x + ((long)b * S + tc * 128) * 256;
    float4 acc = make_float4(0.f, 0.f, 0.f, 0.f);
#pragma unroll 8
    for (int t = tg; t < 128; t += 8) {
        float p = w[t];
        float4 xv = xb[(long)t * 256 + j4];
        acc.x = fmaf(p, xv.x, acc.x);
        acc.y = fmaf(p, xv.y, acc.y);
        acc.z = fmaf(p, xv.z, acc.z);
        acc.w = fmaf(p, xv.w, acc.w);
    }
    redb[tg][jj] = acc;
    __syncthreads();
    if (tg == 0) {
        float4 t0 = redb[0][jj];
#pragma unroll
        for (int p = 1; p < 8; p++) {
            float4 v = redb[p][jj];
            t0.x += v.x; t0.y += v.y; t0.z += v.z; t0.w += v.w;
        }
        float* dst = &xw[(long)b * Dm + j4 * 4];
        atomicAdd(dst + 0, t0.x);
        atomicAdd(dst + 1, t0.y);
        atomicAdd(dst + 2, t0.z);
        atomicAdd(dst + 3, t0.w);
    }
}

// ---------------- r = LN1(accV + bv + x0); reset accV, xw --------------------
__global__ void __launch_bounds__(1024) k_ln1(float* __restrict__ acc,
                                              const float* __restrict__ x, long xstride,
                                              const float* __restrict__ bv,
                                              const float* __restrict__ g1,
                                              const float* __restrict__ b1,
                                              float* __restrict__ xwreset,
                                              float* __restrict__ r) {
    int b = blockIdx.x, j = threadIdx.x;
    __shared__ float sbuf[32];
    float gg = g1[j], bb = b1[j], bvj = bv[j];
    float x0j = x[(long)b * xstride + j];
    cudaGridDependencySynchronize();
    float v = acc[(long)b * Dm + j] + bvj + x0j;
    acc[(long)b * Dm + j] = 0.f;                      // reset for next replay
    xwreset[(long)b * Dm + j] = 0.f;                  // gemv(Wv) upstream done
    float sum = blk_reduce(v, sbuf);
    float sq  = blk_reduce(v * v, sbuf);
    float mu  = sum * (1.f / Dm);
    float var = sq * (1.f / Dm) - mu * mu;
    float rstd = rsqrtf(var + 1e-5f);
    r[(long)b * Dm + j] = (v - mu) * rstd * gg + bb;
}

// ---------------- h = LN2(relu(accD + bd) + r); logits; reset accD -----------
__global__ void __launch_bounds__(1024) k_ln2(float* __restrict__ acc,
                                              const float* __restrict__ bd,
                                              const float* __restrict__ r,
                                              const float* __restrict__ g2,
                                              const float* __restrict__ b2,
                                              const float* __restrict__ Wc,
                                              const float* __restrict__ bc,
                                              float* __restrict__ out) {
    int b = blockIdx.x, j = threadIdx.x;
    __shared__ float sbuf[32];
    float gg = g2[j], bb = b2[j], bdj = bd[j];
    float w0 = Wc[j * 2 + 0], w1 = Wc[j * 2 + 1];
    cudaGridDependencySynchronize();
    float v = fmaxf(acc[(long)b * Dm + j] + bdj, 0.f) + r[(long)b * Dm + j];
    acc[(long)b * Dm + j] = 0.f;                      // reset for next replay
    float sum = blk_reduce(v, sbuf);
    float sq  = blk_reduce(v * v, sbuf);
    float mu  = sum * (1.f / Dm);
    float var = sq * (1.f / Dm) - mu * mu;
    float rstd = rsqrtf(var + 1e-5f);
    float h = (v - mu) * rstd * gg + bb;
    float l0 = blk_reduce(h * w0, sbuf);
    float l1 = blk_reduce(h * w1, sbuf);
    if (j == 0) {
        out[b * 2 + 0] = l0 + bc[0];
        out[b * 2 + 1] = l1 + bc[1];
    }
}

// ---------------- host --------------------------------------------------------
static void launch_ex(const void* fn, dim3 grid, dim3 block, void** args, bool pdl) {
    cudaLaunchConfig_t cfg = {};
    cfg.gridDim = grid;
    cfg.blockDim = block;
    cfg.dynamicSmemBytes = 0;
    cfg.stream = 0;
    cudaLaunchAttribute attr[1];
    attr[0].id = cudaLaunchAttributeProgrammaticStreamSerialization;
    attr[0].val.programmaticStreamSerializationAllowed = 1;
    cfg.attrs = attr;
    cfg.numAttrs = pdl ? 1 : 0;
    cudaLaunchKernelExC(&cfg, fn, args);
}

extern "C" void kernel_launch(void* const* d_in, const int* in_sizes, int n_in,
                              void* d_out, int out_size) {
    const float* x  = (const float*)d_in[0];
    const float* Wq = (const float*)d_in[1];
    const float* bq = (const float*)d_in[2];
    const float* Wk = (const float*)d_in[3];
    // d_in[4] = bk: constant over t in scores -> cancels in softmax; unused.
    const float* Wv = (const float*)d_in[5];
    const float* bv = (const float*)d_in[6];
    const float* Wd = (const float*)d_in[7];
    const float* bd = (const float*)d_in[8];
    const float* g1 = (const float*)d_in[9];
    const float* b1 = (const float*)d_in[10];
    const float* g2 = (const float*)d_in[11];
    const float* b2 = (const float*)d_in[12];
    const float* Wc = (const float*)d_in[13];
    const float* bc = (const float*)d_in[14];
    float* out = (float*)d_out;

    int  B   = out_size / 2;                       // 8
    long xsz = (long)in_sizes[0];
    int  S   = (int)(xsz / ((long)B * Dm));        // 2048
    long xstride = (long)S * Dm;

    float *q0, *u, *xw, *r, *accV, *accD, *sc;
    cudaGetSymbolAddress((void**)&q0,   g_q0);
    cudaGetSymbolAddress((void**)&u,    g_u);
    cudaGetSymbolAddress((void**)&xw,   g_xw);
    cudaGetSymbolAddress((void**)&r,    g_r);
    cudaGetSymbolAddress((void**)&accV, g_accV);
    cudaGetSymbolAddress((void**)&accD, g_accD);
    cudaGetSymbolAddress((void**)&sc,   g_sc);

    // 1. q0 += x0 @ Wq   (first kernel: no PDL wait; starts loading at t=0)
    {
        void* a[] = {(void*)&x, (void*)&xstride, (void*)&Wq, (void*)&q0, (void*)&B};
        launch_ex((const void*)gemv_pdl, dim3(8, 32), dim3(128), a, false);
    }
    // 2. u = Wk @ (q0 + bq)
    {
        void* a[] = {(void*)&Wk, (void*)&q0, (void*)&bq, (void*)&u};
        launch_ex((const void*)k2_u, dim3(Dm / 8), dim3(256), a, true);
    }
    // 3. scores (also zeroes q0 for next replay)
    {
        void* a[] = {(void*)&x, (void*)&u, (void*)&q0, (void*)&sc, (void*)&S};
        launch_ex((const void*)k3a, dim3(S / 16, B), dim3(256), a, true);
    }
    // 4. softmax + weighted accumulate -> xw
    {
        void* a[] = {(void*)&x, (void*)&sc, (void*)&xw, (void*)&S};
        launch_ex((const void*)k3b, dim3((S / 128) * 8, B), dim3(256), a, true);
    }
    // 5. accV += xw @ Wv
    {
        long st = Dm;
        void* a[] = {(void*)&xw, (void*)&st, (void*)&Wv, (void*)&accV, (void*)&B};
        launch_ex((const void*)gemv_pdl, dim3(8, 32), dim3(128), a, true);
    }
    // 6. r = LN1(accV + bv + x0); zero accV, xw
    {
        void* a[] = {(void*)&accV, (void*)&x, (void*)&xstride, (void*)&bv,
                     (void*)&g1, (void*)&b1, (void*)&xw, (void*)&r};
        launch_ex((const void*)k_ln1, dim3(B), dim3(1024), a, true);
    }
    // 7. accD += r @ Wd
    {
        long st = Dm;
        void* a[] = {(void*)&r, (void*)&st, (void*)&Wd, (void*)&accD, (void*)&B};
        launch_ex((const void*)gemv_pdl, dim3(8, 32), dim3(128), a, true);
    }
    // 8. out = LN2(relu(accD + bd) + r) @ Wc + bc; zero accD
    {
        void* a[] = {(void*)&accD, (void*)&bd, (void*)&r, (void*)&g2, (void*)&b2,
                     (void*)&Wc, (void*)&bc, (void*)&out};
        launch_ex((const void*)k_ln2, dim3(B), dim3(1024), a, true);
    }
}